// round 15
// baseline (speedup 1.0000x reference)
#include <cuda_runtime.h>
#include <math_constants.h>

#define BB   32
#define NPF  100
#define FIN  36
#define KNN  11
#define FC   40
#define HH   3600
#define NLL  5
#define EPS_BN 1e-3f
#define NB   225          // grid blocks (225*16 = 3600 cols)
#define NT   256          // threads per block
#define NBUF 3            // cp.async ring depth (prefetch distance 2)

// ---------------- scratch (static, allocation-free) ----------------
__device__ float  d_x[BB * NPF * FC];          // preprocessed features [b][p][f]
__device__ float  d_gT[KNN * FC * BB];         // gathered knn features, transposed [k][b]
__device__ float  d_hAT[HH * BB];              // hidden activations, transposed [k][b]
__device__ float  d_hBT[HH * BB];
__device__ float  d_r[NLL * HH];               // rsqrtf(mvar + eps)
__device__ double d_c2part[BB * NB * 2];       // per-block c2 partials [b][blk][2]
// per-block contiguous weight panels: panel[b] = W[:, 16b:16b+16]
__device__ float  d_W0p[(size_t)KNN * FC * HH];              // [b][440][16]
__device__ float  d_Whp[(size_t)(NLL - 1) * HH * HH];        // [l][b][3600][16]

__device__ unsigned bar_cnt = 0;
__device__ unsigned bar_gen = 0;

// grid-wide barrier: all NB blocks are co-resident by construction (NB=225 <= 2*148).
__device__ __forceinline__ void grid_bar()
{
    __syncthreads();
    if (threadIdx.x == 0) {
        __threadfence();
        unsigned gen = *((volatile unsigned*)&bar_gen);
        if (atomicAdd(&bar_cnt, 1u) == NB - 1) {
            bar_cnt = 0;
            __threadfence();
            *((volatile unsigned*)&bar_gen) = gen + 1;
        } else {
            while (*((volatile unsigned*)&bar_gen) == gen) __nanosleep(64);
        }
        __threadfence();
    }
    __syncthreads();
}

// ---------------- cp.async helpers ----------------
__device__ __forceinline__ void cp16(unsigned d, const void* s)
{
    asm volatile("cp.async.ca.shared.global [%0], [%1], 16;" :: "r"(d), "l"(s));
}
#define CP_COMMIT() asm volatile("cp.async.commit_group;")
#define CP_WAIT(N)  asm volatile("cp.async.wait_group %0;" :: "n"(N))

// packed fp32x2 FMA: two independent IEEE-rn FMAs (identical to scalar sequence)
__device__ __forceinline__ void ffma2(unsigned long long& acc,
                                      unsigned long long x2,
                                      unsigned long long w2)
{
    asm("fma.rn.f32x2 %0, %1, %2, %0;" : "+l"(acc) : "l"(x2), "l"(w2));
}
__device__ __forceinline__ unsigned long long add2(unsigned long long a,
                                                   unsigned long long b)
{
    unsigned long long r;
    asm("add.rn.f32x2 %0, %1, %2;" : "=l"(r) : "l"(a), "l"(b));
    return r;
}

// GEMM layer: (32 x KD) @ (KD x 3600), block owns 16 cols, 8 warps split K.
// Wp = this block's CONTIGUOUS weight panel [KD][16]. 4x4 register tiling.
// Per-accumulator FMA sequence identical to the passing version -> warp partials
// bitwise identical; double cross-warp reduce; unfolded BN in reference op order.
template <int KT, int NTILE>
__device__ __forceinline__ void gemm_layer(const float* __restrict__ inT,
                                           const float* __restrict__ Wp,
                                           float* __restrict__ outT,
                                           int layer,
                                           const float* __restrict__ bias,
                                           const float* __restrict__ gamma,
                                           const float* __restrict__ beta,
                                           const float* __restrict__ mmean,
                                           const float* __restrict__ Wc, int do_c2,
                                           float* s_w, float* s_xt, float* s_red)
{
    constexpr int SUB = KT / 8;       // k-values per warp per tile
    const int col0 = blockIdx.x * 16;
    const int tid  = threadIdx.x;
    const int w    = tid >> 5;
    const int lane = tid & 31;
    const int rg   = lane >> 2;       // row group (0..7) -> rows rg*4..+3
    const int cg   = lane & 3;        // col group (0..3) -> cols cg*4..+3

    const unsigned sw_base = (unsigned)__cvta_generic_to_shared(s_w);
    const unsigned sx_base = (unsigned)__cvta_generic_to_shared(s_xt);

    unsigned long long accA[4][2], accB[4][2];
#pragma unroll
    for (int r = 0; r < 4; r++)
#pragma unroll
        for (int cp = 0; cp < 2; cp++) { accA[r][cp] = 0ull; accB[r][cp] = 0ull; }

    // tile loader: W panel slab [KT][16] and x slab [KT][32] -- both contiguous
    auto load_tile = [&](int buf, int t) {
        const int k0 = t * KT;
#pragma unroll 3
        for (int i = tid; i < KT * 4; i += NT) {
            cp16(sw_base + (unsigned)(buf * KT * 16 + i * 4) * 4,
                 Wp + (size_t)k0 * 16 + i * 4);
        }
#pragma unroll 5
        for (int i = tid; i < KT * 8; i += NT) {
            cp16(sx_base + (unsigned)(buf * KT * 32 + i * 4) * 4,
                 inT + (size_t)k0 * 32 + i * 4);
        }
        CP_COMMIT();
    };

    load_tile(0, 0);
    if (NTILE > 1) load_tile(1, 1);

#pragma unroll 1
    for (int t = 0; t < NTILE; t++) {
        if (t + 2 < NTILE) load_tile((t + 2) % NBUF, t + 2);
        else               CP_COMMIT();
        CP_WAIT(2);                    // tile t's group retired
        __syncthreads();

        const int buf = t % NBUF;
        const float* xp = s_xt + buf * KT * 32 + (w * SUB) * 32 + rg * 4;
        const float* wp = s_w  + buf * KT * 16 + (w * SUB) * 16 + cg * 4;

#pragma unroll 6
        for (int kk = 0; kk < SUB; kk++) {
            float4 xv = *(const float4*)xp;
            ulonglong2 wv = *(const ulonglong2*)wp;
            unsigned long long x2[4];
            asm("mov.b64 %0, {%1, %1};" : "=l"(x2[0]) : "f"(xv.x));
            asm("mov.b64 %0, {%1, %1};" : "=l"(x2[1]) : "f"(xv.y));
            asm("mov.b64 %0, {%1, %1};" : "=l"(x2[2]) : "f"(xv.z));
            asm("mov.b64 %0, {%1, %1};" : "=l"(x2[3]) : "f"(xv.w));
            if (kk & 1) {
#pragma unroll
                for (int r = 0; r < 4; r++) {
                    ffma2(accB[r][0], x2[r], wv.x);
                    ffma2(accB[r][1], x2[r], wv.y);
                }
            } else {
#pragma unroll
                for (int r = 0; r < 4; r++) {
                    ffma2(accA[r][0], x2[r], wv.x);
                    ffma2(accA[r][1], x2[r], wv.y);
                }
            }
            xp += 32; wp += 16;
        }
        __syncthreads();
    }

    // per-warp partial = A + B (packed add = identical scalar adds); layout [w][row][col]
#pragma unroll
    for (int r = 0; r < 4; r++)
#pragma unroll
        for (int cp = 0; cp < 2; cp++) {
            unsigned long long s2 = add2(accA[r][cp], accB[r][cp]);
            unsigned lo, hi;
            asm("mov.b64 {%0, %1}, %2;" : "=r"(lo), "=r"(hi) : "l"(s2));
            int row = rg * 4 + r, c = cg * 4 + 2 * cp;
            s_red[w * 512 + row * 16 + c]     = __uint_as_float(lo);
            s_red[w * 512 + row * 16 + c + 1] = __uint_as_float(hi);
        }
    __syncthreads();
#pragma unroll 1
    for (int o = tid; o < 512; o += NT) {
        double s = 0.0;
#pragma unroll
        for (int ww = 0; ww < 8; ww++) s += (double)s_red[ww * 512 + o];
        int row = o >> 4, c = o & 15;
        int col = col0 + c;
        float sf = (float)s;
        // reference op order: h = dot + bias; u = h - mmean; v = ((gamma*u)*r) + beta
        float h1 = __fadd_rn(sf, bias[col]);
        float u  = __fsub_rn(h1, mmean[col]);
        float v  = __fadd_rn(__fmul_rn(__fmul_rn(gamma[col], u),
                                       d_r[layer * HH + col]),
                             beta[col]);
        v = fmaxf(v, 0.f);
        outT[(size_t)col * 32 + row] = v;
        if (do_c2) {
            double p0 = (double)v * (double)Wc[2 * col];
            double p1 = (double)v * (double)Wc[2 * col + 1];
#pragma unroll
            for (int off = 8; off; off >>= 1) {
                p0 += __shfl_down_sync(0xffffffffu, p0, off, 16);
                p1 += __shfl_down_sync(0xffffffffu, p1, off, 16);
            }
            if ((o & 15) == 0) {
                d_c2part[((size_t)row * NB + blockIdx.x) * 2 + 0] = p0;
                d_c2part[((size_t)row * NB + blockIdx.x) * 2 + 1] = p1;
            }
        }
    }
    __syncthreads();
}

__global__ void __launch_bounds__(NT, 2)
mega_kernel(const float* __restrict__ xx,
            const float* __restrict__ e1, const float* __restrict__ e2,
            const float* __restrict__ e3,
            const float* __restrict__ mean, const float* __restrict__ stdv,
            const float* __restrict__ vmin, const float* __restrict__ vmax,
            const float* __restrict__ W0,  const float* __restrict__ b0,
            const float* __restrict__ Wh,  const float* __restrict__ bh,
            const float* __restrict__ gamma, const float* __restrict__ beta,
            const float* __restrict__ mmean, const float* __restrict__ mvar,
            const float* __restrict__ Wc,  const float* __restrict__ bc,
            const float* __restrict__ W2,  const float* __restrict__ b2,
            const float* __restrict__ W100,const float* __restrict__ b100,
            float* __restrict__ out)
{
    extern __shared__ __align__(16) float smem_dyn[];
    float* s_w   = smem_dyn;                       // NBUF * 144*16 = 6912
    float* s_xt  = s_w + NBUF * 144 * 16;          // NBUF * 144*32 = 13824
    float* s_red = s_xt + NBUF * 144 * 32;         // 4096 (8B aligned for double use)
    float* s_sel = s_red + 4096;                   // 128
    int*   s_idx = (int*)(s_sel + 128);            // 16

    const int bid = blockIdx.x;
    const int tid = threadIdx.x;
    const int gtid = bid * NT + tid;

    // -------- preprocessing (contraction-free IEEE ops) --------
    for (int idx = gtid; idx < BB * NPF; idx += NB * NT) {
        const float* r = xx + (size_t)idx * FIN;
        float* o = d_x + (size_t)idx * FC;
        int i1 = (int)fabsf(r[0]);
        int i2 = (int)fabsf(r[1]);
        int i3 = (int)fabsf(r[2]);
        o[0] = e1[i1 * 2]; o[1] = e1[i1 * 2 + 1];
        o[2] = e2[i2 * 2]; o[3] = e2[i2 * 2 + 1];
        o[4] = e3[i3 * 2]; o[5] = e3[i3 * 2 + 1];
#pragma unroll
        for (int f = 2; f < FIN; f++) {
            float v = r[f];
            if (f >= 3) {
                float y = __fdiv_rn(__fsub_rn(v, mean[f]), stdv[f]);
                y = fminf(fmaxf(y, -5.f), 5.f);
                float sc = __fdiv_rn(2.f, __fsub_rn(vmax[f], vmin[f]));
                y = __fsub_rn(__fmul_rn(sc, __fsub_rn(y, vmin[f])), 1.f);
                y = fminf(fmaxf(y, -1.f), 1.f);
                v = y;
            }
            o[6 + f - 2] = v;
        }
    }
    // -------- per-channel rsqrt (matches lax.rsqrt lowering) --------
    for (int idx = gtid; idx < NLL * HH; idx += NB * NT) {
        d_r[idx] = rsqrtf(__fadd_rn(mvar[idx], EPS_BN));
    }
    // -------- repack weights into per-block contiguous panels --------
    for (size_t i = (size_t)gtid * 4; i < (size_t)KNN * FC * HH; i += (size_t)NB * NT * 4) {
        int k   = (int)(i / HH);
        int col = (int)(i - (size_t)k * HH);
        float4 v = *(const float4*)(W0 + i);
        *(float4*)(d_W0p + ((size_t)(col >> 4) * (KNN * FC) + k) * 16 + (col & 15)) = v;
    }
    for (size_t i = (size_t)gtid * 4; i < (size_t)(NLL - 1) * HH * HH; i += (size_t)NB * NT * 4) {
        size_t r = i % ((size_t)HH * HH);
        int l    = (int)(i / ((size_t)HH * HH));
        int k    = (int)(r / HH);
        int col  = (int)(r - (size_t)k * HH);
        float4 v = *(const float4*)(Wh + i);
        *(float4*)(d_Whp + (((size_t)l * NB + (col >> 4)) * HH + k) * 16 + (col & 15)) = v;
    }
    grid_bar();

    const float* W0p_blk = d_W0p + (size_t)bid * (KNN * FC) * 16;
    const float* Whp_blk0 = d_Whp + ((size_t)0 * NB + bid) * HH * 16;
    const float* Whp_blk1 = d_Whp + ((size_t)1 * NB + bid) * HH * 16;
    const float* Whp_blk2 = d_Whp + ((size_t)2 * NB + bid) * HH * 16;
    const float* Whp_blk3 = d_Whp + ((size_t)3 * NB + bid) * HH * 16;

    // -------- 100 sequential knn+MLP steps --------
#pragma unroll 1
    for (int it = 0; it < NPF; it++) {
        // ---- selection (blocks 0..31, one per batch element) ----
        if (bid < BB) {
            const int b = bid;
            const float* xb = d_x + (size_t)b * NPF * FC;
            float r0, r1;
            if (it == 0) {
                r0 = xb[12];  // ETA_C of particle 0
                r1 = xb[13];  // PHI_C
            } else {
                // deterministic fp64 tree over the 225 per-block partials
                double* dred = (double*)s_red;
                double v0 = 0.0, v1 = 0.0;
                if (tid < NB) {
                    v0 = d_c2part[((size_t)b * NB + tid) * 2 + 0];
                    v1 = d_c2part[((size_t)b * NB + tid) * 2 + 1];
                }
                dred[tid] = v0; dred[NT + tid] = v1;
                __syncthreads();
                for (int s = NT / 2; s > 0; s >>= 1) {
                    if (tid < s) {
                        dred[tid]      += dred[tid + s];
                        dred[NT + tid] += dred[NT + tid + s];
                    }
                    __syncthreads();
                }
                r0 = __fadd_rn((float)dred[0],  bc[0]);
                r1 = __fadd_rn((float)dred[NT], bc[1]);
                __syncthreads();
            }
            if (tid < NPF) {
                float de = __fsub_rn(xb[tid * FC + 12], r0);
                float dp = __fsub_rn(xb[tid * FC + 13], r1);
                s_sel[tid] = sqrtf(__fadd_rn(__fmul_rn(de, de), __fmul_rn(dp, dp)));
            }
            __syncthreads();
            // warp-parallel stable top-11 (exact (d, idx) order -> identical picks)
            if (tid < 32) {
                const int lane = tid;
#pragma unroll 1
                for (int s = 0; s < KNN; s++) {
                    float best = CUDART_INF_F; int bi = NPF;
                    for (int p = lane; p < NPF; p += 32) {
                        float v = s_sel[p];
                        if (v < best || (v == best && p < bi)) { best = v; bi = p; }
                    }
#pragma unroll
                    for (int o = 16; o; o >>= 1) {
                        float ov = __shfl_down_sync(0xffffffffu, best, o);
                        int   oi = __shfl_down_sync(0xffffffffu, bi, o);
                        if (ov < best || (ov == best && oi < bi)) { best = ov; bi = oi; }
                    }
                    bi = __shfl_sync(0xffffffffu, bi, 0);
                    if (lane == 0) { s_idx[s] = bi; s_sel[bi] = CUDART_INF_F; }
                    __syncwarp();
                }
            }
            __syncthreads();
            // gather into transposed layout [440][32]
            for (int i = tid; i < KNN * FC; i += NT) {
                int s = i / FC, f = i - s * FC;
                d_gT[(size_t)i * 32 + b] = xb[s_idx[s] * FC + f];
            }
        }
        grid_bar();

        // ---- MLP: layer 0 (K=440, 11 tiles of 40), layers 1..4 (K=3600, 25 tiles of 144)
        gemm_layer<40, 11>(d_gT, W0p_blk, d_hAT, 0,
                           b0, gamma, beta, mmean, Wc, 0, s_w, s_xt, s_red);
        grid_bar();
        gemm_layer<144, 25>(d_hAT, Whp_blk0, d_hBT, 1,
                            bh,        gamma + HH,   beta + HH,   mmean + HH,
                            Wc, 0, s_w, s_xt, s_red); grid_bar();
        gemm_layer<144, 25>(d_hBT, Whp_blk1, d_hAT, 2,
                            bh + HH,   gamma + 2*HH, beta + 2*HH, mmean + 2*HH,
                            Wc, 0, s_w, s_xt, s_red); grid_bar();
        gemm_layer<144, 25>(d_hAT, Whp_blk2, d_hBT, 3,
                            bh + 2*HH, gamma + 3*HH, beta + 3*HH, mmean + 3*HH,
                            Wc, 0, s_w, s_xt, s_red); grid_bar();
        gemm_layer<144, 25>(d_hBT, Whp_blk3, d_hAT, 4,
                            bh + 3*HH, gamma + 4*HH, beta + 4*HH, mmean + 4*HH,
                            Wc, 1, s_w, s_xt, s_red); grid_bar();
    }

    // -------- final epilogue (blocks 0..31) --------
    if (bid < BB) {
        const int b = bid;
        float* slog = s_sel;          // 100 logits
        float* sred = s_red;          // 256 reduce
        int w = tid >> 5, lane = tid & 31;

        // logits h @ W100 + b100
        for (int p = w; p < NPF; p += 8) {
            float acc = 0.f;
            for (int k = lane; k < HH; k += 32)
                acc += d_hAT[(size_t)k * 32 + b] * W100[(size_t)k * NPF + p];
#pragma unroll
            for (int o = 16; o; o >>= 1) acc += __shfl_down_sync(0xffffffffu, acc, o);
            if (lane == 0) slog[p] = acc + b100[p];
        }
        // x2 dots
        float a0 = 0.f, a1 = 0.f;
        for (int k = tid; k < HH; k += NT) {
            float hv = d_hAT[(size_t)k * 32 + b];
            a0 += hv * W2[2 * k];
            a1 += hv * W2[2 * k + 1];
        }
        __syncthreads();
        sred[tid] = a0; __syncthreads();
        for (int s = 128; s > 0; s >>= 1) { if (tid < s) sred[tid] += sred[tid + s]; __syncthreads(); }
        float x20 = sred[0] + b2[0]; __syncthreads();
        sred[tid] = a1; __syncthreads();
        for (int s = 128; s > 0; s >>= 1) { if (tid < s) sred[tid] += sred[tid + s]; __syncthreads(); }
        float x21 = sred[0] + b2[1]; __syncthreads();

        // softmax
        float mx = -CUDART_INF_F;
        for (int p = tid; p < NPF; p += NT) mx = fmaxf(mx, slog[p]);
        sred[tid] = mx; __syncthreads();
        for (int s = 128; s > 0; s >>= 1) { if (tid < s) sred[tid] = fmaxf(sred[tid], sred[tid + s]); __syncthreads(); }
        mx = sred[0]; __syncthreads();
        float es = 0.f;
        for (int p = tid; p < NPF; p += NT) {
            float e = expf(slog[p] - mx);
            slog[p] = e;
            es += e;
        }
        sred[tid] = es; __syncthreads();
        for (int s = 128; s > 0; s >>= 1) { if (tid < s) sred[tid] += sred[tid + s]; __syncthreads(); }
        es = sred[0]; __syncthreads();

        // weighted physics sums
        float px = 0.f, py = 0.f, pz = 0.f, E = 0.f;
        for (int p = tid; p < NPF; p += NT) {
            const float* xr = xx + ((size_t)b * NPF + p) * FIN;
            float wv = (slog[p] / es) * xr[7];
            px += xr[3] * wv; py += xr[4] * wv;
            pz += xr[5] * wv; E  += xr[6] * wv;
        }
        sred[tid] = px; __syncthreads();
        for (int s = 128; s > 0; s >>= 1) { if (tid < s) sred[tid] += sred[tid + s]; __syncthreads(); }
        px = sred[0]; __syncthreads();
        sred[tid] = py; __syncthreads();
        for (int s = 128; s > 0; s >>= 1) { if (tid < s) sred[tid] += sred[tid + s]; __syncthreads(); }
        py = sred[0]; __syncthreads();
        sred[tid] = pz; __syncthreads();
        for (int s = 128; s > 0; s >>= 1) { if (tid < s) sred[tid] += sred[tid + s]; __syncthreads(); }
        pz = sred[0]; __syncthreads();
        sred[tid] = E; __syncthreads();
        for (int s = 128; s > 0; s >>= 1) { if (tid < s) sred[tid] += sred[tid + s]; __syncthreads(); }
        E = sred[0]; __syncthreads();

        if (tid == 0) {
            float px2 = px * px, py2 = py * py, pz2 = pz * pz;
            float pt = sqrtf(px2 + py2);
            float mass2 = E * E - px2 - py2 - pz2;
            float absp = sqrtf(px2 + py2 + pz2);
            float cosT = (absp == 0.f) ? 1.f : pz / absp;
            bool okc = cosT * cosT < 1.f;
            float ratio = okc ? (1.f - cosT) / (1.f + cosT) : 1.f;
            float eta = okc ? -0.5f * logf(ratio) : 0.f;
            float phi = (px == 0.f && py == 0.f) ? 0.f : atan2f(py, px);
            out[b * 6 + 0] = x20;
            out[b * 6 + 1] = x21;
            out[b * 6 + 2] = pt;
            out[b * 6 + 3] = eta;
            out[b * 6 + 4] = phi;
            out[b * 6 + 5] = mass2;
        }
    }
}

// ---------------- launcher: ONE node in the graph ----------------
extern "C" void kernel_launch(void* const* d_in, const int* in_sizes, int n_in,
                              void* d_out, int out_size)
{
    // dynamic smem: NBUF*(144*16 + 144*32) + 4096 + 128 + 16 ints
    const int smem_bytes = (NBUF * 144 * 16 + NBUF * 144 * 32 + 4096 + 128 + 16) * 4;
    static int attr_done = 0;
    if (!attr_done) {
        cudaFuncSetAttribute(mega_kernel,
                             cudaFuncAttributeMaxDynamicSharedMemorySize, smem_bytes);
        attr_done = 1;
    }
    mega_kernel<<<NB, NT, smem_bytes>>>(
        (const float*)d_in[0],  (const float*)d_in[1],  (const float*)d_in[2],
        (const float*)d_in[3],  (const float*)d_in[4],  (const float*)d_in[5],
        (const float*)d_in[6],  (const float*)d_in[7],  (const float*)d_in[8],
        (const float*)d_in[9],  (const float*)d_in[10], (const float*)d_in[11],
        (const float*)d_in[12], (const float*)d_in[13], (const float*)d_in[14],
        (const float*)d_in[15], (const float*)d_in[16], (const float*)d_in[17],
        (const float*)d_in[18], (const float*)d_in[19], (const float*)d_in[20],
        (const float*)d_in[21], (float*)d_out);
}